// round 14
// baseline (speedup 1.0000x reference)
#include <cuda_runtime.h>
#include <cuda_bf16.h>
#include <cstddef>
#include <cstdint>

#define NROWS 32768
#define EDIM  1024
#define MSIZE 2048
typedef __nv_bfloat16 bf16;

// ---------------- scratch ----------------------------------------------------
__device__ float g_part[4096];
__device__ float g_scal[8];           // 0 xmax, 1 hmax, 2 wsk, 3 wso
__device__ bf16  g_qxb [(size_t)NROWS * EDIM];    // qx bf16 ; reused as qh int8
__device__ bf16  g_qwkT[(size_t)EDIM * EDIM];
__device__ signed char g_qwo8[(size_t)EDIM * EDIM];
__device__ bf16  g_mkhi[(size_t)MSIZE * EDIM];
__device__ bf16  g_mklo[(size_t)MSIZE * EDIM];
__device__ bf16  g_ghi [(size_t)MSIZE * EDIM];
__device__ bf16  g_glo [(size_t)MSIZE * EDIM];
__device__ bf16  g_mhiT[(size_t)EDIM * MSIZE];
__device__ bf16  g_mloT[(size_t)EDIM * MSIZE];
__device__ float g_c   [MSIZE];
__device__ float g_sim [(size_t)NROWS * MSIZE];
__device__ bf16  g_ahi [(size_t)NROWS * MSIZE];
__device__ bf16  g_alo [(size_t)NROWS * MSIZE];
__device__ float g_h   [(size_t)NROWS * EDIM];

// ---------------- helpers ----------------------------------------------------
__device__ __forceinline__ uint32_t smem_u32(const void* p) {
    uint32_t a;
    asm("{ .reg .u64 t; cvta.to.shared.u64 t, %1; cvt.u32.u64 %0, t; }" : "=r"(a) : "l"(p));
    return a;
}
__device__ __forceinline__ uint32_t sw_addr(uint32_t base, int r, int g) {
    return base + r * 128 + ((g ^ (r & 7)) << 4);
}
__device__ __forceinline__ void cp16(uint32_t s, const void* g) {
    asm volatile("cp.async.cg.shared.global [%0], [%1], 16;" :: "r"(s), "l"(g));
}
#define CP_COMMIT() asm volatile("cp.async.commit_group;" ::: "memory")
#define CP_WAIT0()  asm volatile("cp.async.wait_group 0;" ::: "memory")
#define LDSM4(r0, r1, r2, r3, addr) \
    asm volatile("ldmatrix.sync.aligned.m8n8.x4.shared.b16 {%0,%1,%2,%3}, [%4];" \
                 : "=r"(r0), "=r"(r1), "=r"(r2), "=r"(r3) : "r"(addr))
#define MMA_BF16(c, a, b0r, b1r) \
    asm volatile("mma.sync.aligned.m16n8k16.row.col.f32.bf16.bf16.f32 " \
                 "{%0,%1,%2,%3}, {%4,%5,%6,%7}, {%8,%9}, {%0,%1,%2,%3};" \
                 : "+f"((c)[0]), "+f"((c)[1]), "+f"((c)[2]), "+f"((c)[3]) \
                 : "r"((a)[0]), "r"((a)[1]), "r"((a)[2]), "r"((a)[3]), "r"(b0r), "r"(b1r))
#define MMA_S8(c, a, b0r, b1r) \
    asm volatile("mma.sync.aligned.m16n8k32.row.col.s32.s8.s8.s32 " \
                 "{%0,%1,%2,%3}, {%4,%5,%6,%7}, {%8,%9}, {%0,%1,%2,%3};" \
                 : "+r"((c)[0]), "+r"((c)[1]), "+r"((c)[2]), "+r"((c)[3]) \
                 : "r"((a)[0]), "r"((a)[1]), "r"((a)[2]), "r"((a)[3]), "r"(b0r), "r"(b1r))

// ---------------- fused prologue ---------------------------------------------
// blocks [0,2048): x absmax -> part[0..2048)
// [2048,2560): Wk abssum -> part[2048+] ; [2560,3072): Wo abssum -> part[2560+]
// [3072, 3072+8192): mk split -> mkhi/mklo
__global__ void prep_all(const float* __restrict__ x, const float* __restrict__ mk,
                         const float* __restrict__ Wk, const float* __restrict__ Wo,
                         bf16* __restrict__ mkhi, bf16* __restrict__ mklo,
                         float* __restrict__ part) {
    const int b = blockIdx.x, tid = threadIdx.x;
    __shared__ float red[256];
    if (b < 2048) {
        const float4* x4 = (const float4*)x;
        const size_t n4 = (size_t)NROWS * EDIM / 4;
        float m = 0.f;
        for (size_t i = (size_t)b * 256 + tid; i < n4; i += (size_t)2048 * 256) {
            float4 v = x4[i];
            m = fmaxf(m, fmaxf(fmaxf(fabsf(v.x), fabsf(v.y)), fmaxf(fabsf(v.z), fabsf(v.w))));
        }
        red[tid] = m; __syncthreads();
        for (int s = 128; s > 0; s >>= 1) {
            if (tid < s) red[tid] = fmaxf(red[tid], red[tid + s]);
            __syncthreads();
        }
        if (tid == 0) part[b] = red[0];
    } else if (b < 3072) {
        const float4* w4 = (const float4*)(b < 2560 ? Wk : Wo);
        const int bb = (b < 2560) ? b - 2048 : b - 2560;
        const size_t n4 = (size_t)EDIM * EDIM / 4;
        float s = 0.f;
        for (size_t i = (size_t)bb * 256 + tid; i < n4; i += (size_t)512 * 256) {
            float4 v = w4[i];
            s += fabsf(v.x) + fabsf(v.y) + fabsf(v.z) + fabsf(v.w);
        }
        red[tid] = s; __syncthreads();
        for (int st = 128; st > 0; st >>= 1) {
            if (tid < st) red[tid] += red[tid + st];
            __syncthreads();
        }
        if (tid == 0) part[(b < 2560 ? 2048 : 2560) + bb] = red[0];
    } else {
        size_t i = (size_t)(b - 3072) * 256 + tid;
        if (i < (size_t)MSIZE * EDIM) {
            float v = mk[i];
            bf16 h = __float2bfloat16(v);
            mkhi[i] = h;
            mklo[i] = __float2bfloat16(v - __bfloat162float(h));
        }
    }
}

// xmax, wsk, wso in one block
__global__ void finalize3(const float* __restrict__ part, float* __restrict__ scal) {
    __shared__ float red[256];
    const int tid = threadIdx.x;
    const float n = (float)((size_t)EDIM * EDIM);
    float m = 0.f;
    for (int i = tid; i < 2048; i += 256) m = fmaxf(m, part[i]);
    red[tid] = m; __syncthreads();
    for (int s = 128; s > 0; s >>= 1) {
        if (tid < s) red[tid] = fmaxf(red[tid], red[tid + s]);
        __syncthreads();
    }
    if (tid == 0) scal[0] = red[0];
    __syncthreads();
    float s1 = 0.f;
    for (int i = tid; i < 512; i += 256) s1 += part[2048 + i];
    red[tid] = s1; __syncthreads();
    for (int st = 128; st > 0; st >>= 1) {
        if (tid < st) red[tid] += red[tid + st];
        __syncthreads();
    }
    if (tid == 0) scal[2] = __fdiv_rn(red[0], n);
    __syncthreads();
    float s2 = 0.f;
    for (int i = tid; i < 512; i += 256) s2 += part[2560 + i];
    red[tid] = s2; __syncthreads();
    for (int st = 128; st > 0; st >>= 1) {
        if (tid < st) red[tid] += red[tid + st];
        __syncthreads();
    }
    if (tid == 0) scal[3] = __fdiv_rn(red[0], n);
}

__global__ void finalize_max(const float* __restrict__ part, int npart, float* __restrict__ out) {
    __shared__ float red[256];
    float m = 0.f;
    for (int i = threadIdx.x; i < npart; i += 256) m = fmaxf(m, part[i]);
    red[threadIdx.x] = m; __syncthreads();
    for (int s = 128; s > 0; s >>= 1) {
        if (threadIdx.x < s) red[threadIdx.x] = fmaxf(red[threadIdx.x], red[threadIdx.x + s]);
        __syncthreads();
    }
    if (threadIdx.x == 0) out[0] = red[0];
}

// ---------------- quantize / split / transpose -------------------------------
__global__ void quantize_act_bf16(const float* __restrict__ x, bf16* __restrict__ q,
                                  const float* __restrict__ amax, size_t n4) {
    size_t i = (size_t)blockIdx.x * blockDim.x + threadIdx.x;
    if (i >= n4) return;
    float iscale = __fdiv_rn(amax[0], 127.0f);
    float4 v = ((const float4*)x)[i];
    float r0 = fminf(fmaxf(rintf(__fdiv_rn(v.x, iscale)), -128.f), 127.f);
    float r1 = fminf(fmaxf(rintf(__fdiv_rn(v.y, iscale)), -128.f), 127.f);
    float r2 = fminf(fmaxf(rintf(__fdiv_rn(v.z, iscale)), -128.f), 127.f);
    float r3 = fminf(fmaxf(rintf(__fdiv_rn(v.w, iscale)), -128.f), 127.f);
    bf16* o = q + i * 4;
    o[0] = __float2bfloat16(r0); o[1] = __float2bfloat16(r1);
    o[2] = __float2bfloat16(r2); o[3] = __float2bfloat16(r3);
}

__global__ void quantize_act_i8(const float* __restrict__ x, signed char* __restrict__ q,
                                const float* __restrict__ amax, size_t n4) {
    size_t i = (size_t)blockIdx.x * blockDim.x + threadIdx.x;
    if (i >= n4) return;
    float iscale = __fdiv_rn(amax[0], 127.0f);
    float4 v = ((const float4*)x)[i];
    char4 o; float r;
    r = rintf(__fdiv_rn(v.x, iscale)); r = fminf(fmaxf(r, -128.f), 127.f); o.x = (signed char)r;
    r = rintf(__fdiv_rn(v.y, iscale)); r = fminf(fmaxf(r, -128.f), 127.f); o.y = (signed char)r;
    r = rintf(__fdiv_rn(v.z, iscale)); r = fminf(fmaxf(r, -128.f), 127.f); o.z = (signed char)r;
    r = rintf(__fdiv_rn(v.w, iscale)); r = fminf(fmaxf(r, -128.f), 127.f); o.w = (signed char)r;
    ((char4*)q)[i] = o;
}

__global__ void quantize_w_i8(const float* __restrict__ W, signed char* __restrict__ q,
                              const float* __restrict__ wscale, size_t n4) {
    size_t i = (size_t)blockIdx.x * blockDim.x + threadIdx.x;
    if (i >= n4) return;
    float thr = 0.5f * wscale[0];
    float4 v = ((const float4*)W)[i];
    char4 o;
    o.x = (fabsf(v.x) > thr) ? (v.x > 0.f ? 1 : -1) : 0;
    o.y = (fabsf(v.y) > thr) ? (v.y > 0.f ? 1 : -1) : 0;
    o.z = (fabsf(v.z) > thr) ? (v.z > 0.f ? 1 : -1) : 0;
    o.w = (fabsf(v.w) > thr) ? (v.w > 0.f ? 1 : -1) : 0;
    ((char4*)q)[i] = o;
}

// quantize Wk to bf16 ternary, transposed: q[i,d] = quant(W[d,i])
__global__ void tq_wkT(const float* __restrict__ W, bf16* __restrict__ q,
                       const float* __restrict__ scal) {
    __shared__ float t[32][33];
    int bd = blockIdx.y * 32, bi = blockIdx.x * 32;
    for (int j = threadIdx.y; j < 32; j += 8)
        t[j][threadIdx.x] = W[(size_t)(bd + j) * EDIM + bi + threadIdx.x];
    __syncthreads();
    float thr = 0.5f * scal[2];
    for (int j = threadIdx.y; j < 32; j += 8) {
        float v = t[threadIdx.x][j];
        float o = (fabsf(v) > thr) ? (v > 0.f ? 1.f : -1.f) : 0.f;
        q[(size_t)(bi + j) * EDIM + bd + threadIdx.x] = __float2bfloat16(o);
    }
}

// mv [MSIZE, EDIM] -> transposed split [EDIM, MSIZE]
__global__ void transpose_split(const float* __restrict__ mv, bf16* __restrict__ hi,
                                bf16* __restrict__ lo) {
    __shared__ float t[32][33];
    int bx = blockIdx.x * 32, by = blockIdx.y * 32;
    for (int i = threadIdx.y; i < 32; i += 8)
        t[i][threadIdx.x] = mv[(size_t)(by + i) * EDIM + bx + threadIdx.x];
    __syncthreads();
    for (int i = threadIdx.y; i < 32; i += 8) {
        float v = t[threadIdx.x][i];
        bf16 h = __float2bfloat16(v);
        size_t o = (size_t)(bx + i) * MSIZE + by + threadIdx.x;
        hi[o] = h;
        lo[o] = __float2bfloat16(v - __bfloat162float(h));
    }
}

__global__ void cvec_k(const float* __restrict__ mk, const float* __restrict__ bk,
                       float* __restrict__ c) {
    int m = blockIdx.x * 8 + (threadIdx.x >> 5);
    int lane = threadIdx.x & 31;
    const float4* row = (const float4*)(mk + (size_t)m * EDIM);
    const float4* b4 = (const float4*)bk;
    float s = 0.f;
    for (int i = lane; i < EDIM / 4; i += 32) {
        float4 a = row[i], b = b4[i];
        s += a.x * b.x + a.y * b.y + a.z * b.z + a.w * b.w;
    }
    for (int o = 16; o > 0; o >>= 1) s += __shfl_xor_sync(0xffffffffu, s, o);
    if (lane == 0) c[m] = s;
}

// -------- row softmax (+ c[m]/32), emit 2-level bf16 attn --------------------
__global__ void softmax_split(const float* __restrict__ S, const float* __restrict__ c,
                              bf16* __restrict__ ahi, bf16* __restrict__ alo) {
    const size_t row = blockIdx.x;
    const float* p = S + row * (size_t)MSIZE;
    const int tid = threadIdx.x;
    float v[8];
#pragma unroll
    for (int i = 0; i < 8; i++) v[i] = p[tid + i * 256] + c[tid + i * 256] * 0.03125f;
    float m = v[0];
#pragma unroll
    for (int i = 1; i < 8; i++) m = fmaxf(m, v[i]);
    __shared__ float red[256];
    red[tid] = m; __syncthreads();
    for (int s = 128; s > 0; s >>= 1) {
        if (tid < s) red[tid] = fmaxf(red[tid], red[tid + s]);
        __syncthreads();
    }
    const float rowmax = red[0];
    __syncthreads();
    float sum = 0.f;
#pragma unroll
    for (int i = 0; i < 8; i++) { v[i] = expf(v[i] - rowmax); sum += v[i]; }
    red[tid] = sum; __syncthreads();
    for (int s = 128; s > 0; s >>= 1) {
        if (tid < s) red[tid] += red[tid + s];
        __syncthreads();
    }
    const float inv = __fdiv_rn(1.0f, red[0]);
#pragma unroll
    for (int i = 0; i < 8; i++) {
        float a = v[i] * inv;
        bf16 h = __float2bfloat16(a);
        size_t o = row * (size_t)MSIZE + tid + i * 256;
        ahi[o] = h;
        alo[o] = __float2bfloat16(a - __bfloat162float(h));
    }
}

// ======= bf16 mma.sync GEMM NT, 128x128 tile, term-fused single K-sweep ======
// (identical to R11 best: simple 2-stage double buffer, wait 0)
__global__ __launch_bounds__(256)
void tc_gemm(const bf16* A0, const bf16* A1, const bf16* B0, const bf16* B1,
             int nA, int nB, int tmask, int K,
             float* __restrict__ C, const float* __restrict__ aux,
             const float* __restrict__ scal, float* __restrict__ part,
             int mode, int M, bf16* __restrict__ Ohi, bf16* __restrict__ Olo) {
    extern __shared__ char dsm[];
    __shared__ float red[256];
    const int tid = threadIdx.x, l = tid & 31, w = tid >> 5;
    const int bm = blockIdx.y * 128, bn = blockIdx.x * 128;
    const int wm = (w & 1) * 64, wn = (w >> 1) * 32;
    const int kchunks = K >> 6;
    const int ntiles = nA + nB;
    const uint32_t stageBytes = (uint32_t)ntiles * 16384u;
    const uint32_t sbase = smem_u32(dsm);

    const bf16* tp[4]; int rbase[4];
    {
        int n = 0;
        tp[n] = A0; rbase[n] = bm; n++;
        if (nA > 1) { tp[n] = A1; rbase[n] = bm; n++; }
        tp[n] = B0; rbase[n] = bn; n++;
        if (nB > 1) { tp[n] = B1; rbase[n] = bn; n++; }
    }

    float acc[4][4][4];
#pragma unroll
    for (int i = 0; i < 4; i++)
#pragma unroll
        for (int j = 0; j < 4; j++)
#pragma unroll
            for (int k = 0; k < 4; k++) acc[i][j][k] = 0.f;

    const int lr = tid >> 3, lg = tid & 7;
    for (int t = 0; t < ntiles; t++) {
        const bf16* gp = tp[t] + (size_t)(rbase[t] + lr) * K + lg * 8;
        uint32_t s = sbase + t * 16384u;
#pragma unroll
        for (int i = 0; i < 4; i++)
            cp16(sw_addr(s, lr + i * 32, lg), gp + (size_t)i * 32 * K);
    }
    CP_COMMIT();
    CP_WAIT0();
    __syncthreads();

    for (int ch = 0; ch < kchunks; ch++) {
        const uint32_t st = sbase + (uint32_t)(ch & 1) * stageBytes;
        if (ch + 1 < kchunks) {
            const uint32_t nst = sbase + (uint32_t)((ch + 1) & 1) * stageBytes;
            for (int t = 0; t < ntiles; t++) {
                const bf16* gp = tp[t] + (size_t)(rbase[t] + lr) * K + (ch + 1) * 64 + lg * 8;
                uint32_t s = nst + t * 16384u;
#pragma unroll
                for (int i = 0; i < 4; i++)
                    cp16(sw_addr(s, lr + i * 32, lg), gp + (size_t)i * 32 * K);
            }
            CP_COMMIT();
        }
        const int rA = wm + (l & 15);
        const int rB = wn + (l & 7) + ((l & 16) ? 8 : 0);
        for (int t = 0; t < 4; t++) {
            if (!((tmask >> t) & 1)) continue;
            const uint32_t sA = st + (uint32_t)(t >> 1) * 16384u;
            const uint32_t sB = st + (uint32_t)(nA + (t & 1)) * 16384u;
#pragma unroll
            for (int ks = 0; ks < 4; ks++) {
                uint32_t a[4][4], b[2][4];
                const int gA = ks * 2 + (l >> 4);
                const int gB = ks * 2 + ((l >> 3) & 1);
#pragma unroll
                for (int mt = 0; mt < 4; mt++)
                    LDSM4(a[mt][0], a[mt][1], a[mt][2], a[mt][3], sw_addr(sA, rA + mt * 16, gA));
#pragma unroll
                for (int bp = 0; bp < 2; bp++)
                    LDSM4(b[bp][0], b[bp][1], b[bp][2], b[bp][3], sw_addr(sB, rB + bp * 16, gB));
#pragma unroll
                for (int mt = 0; mt < 4; mt++)
#pragma unroll
                    for (int nt = 0; nt < 4; nt++)
                        MMA_BF16(acc[mt][nt], a[mt], b[nt >> 1][(nt & 1) * 2], b[nt >> 1][(nt & 1) * 2 + 1]);
            }
        }
        if (ch + 1 < kchunks) CP_WAIT0();
        __syncthreads();
    }

    float alpha = 1.f;
    if (mode == 0) alpha = 0.03125f * scal[2] * __fdiv_rn(scal[0], 127.0f);
    float lmax = 0.f;
    const int rr = bm + wm + (l >> 2);
    const int cbs = bn + wn + (l & 3) * 2;
#pragma unroll
    for (int mt = 0; mt < 4; mt++) {
        int r0 = rr + mt * 16;
#pragma unroll
        for (int nt = 0; nt < 4; nt++) {
            int cc = cbs + nt * 8;
            float v0 = acc[mt][nt][0], v1 = acc[mt][nt][1];
            float v2 = acc[mt][nt][2], v3 = acc[mt][nt][3];
            if (mode == 3) {
                bf16 h0 = __float2bfloat16(v0), h1 = __float2bfloat16(v1);
                bf16 h2 = __float2bfloat16(v2), h3 = __float2bfloat16(v3);
                size_t o0 = (size_t)r0 * M + cc, o1 = (size_t)(r0 + 8) * M + cc;
                Ohi[o0] = h0; Ohi[o0 + 1] = h1; Ohi[o1] = h2; Ohi[o1 + 1] = h3;
                Olo[o0] = __float2bfloat16(v0 - __bfloat162float(h0));
                Olo[o0 + 1] = __float2bfloat16(v1 - __bfloat162float(h1));
                Olo[o1] = __float2bfloat16(v2 - __bfloat162float(h2));
                Olo[o1 + 1] = __float2bfloat16(v3 - __bfloat162float(h3));
                continue;
            }
            float* p0 = C + (size_t)r0 * M + cc;
            float* p1 = p0 + (size_t)8 * M;
            if (mode == 1) {
                const float* x0 = aux + (size_t)r0 * M + cc;
                const float* x1 = x0 + (size_t)8 * M;
                v0 += x0[0]; v1 += x0[1]; v2 += x1[0]; v3 += x1[1];
                lmax = fmaxf(lmax, fmaxf(fmaxf(fabsf(v0), fabsf(v1)), fmaxf(fabsf(v2), fabsf(v3))));
            } else if (mode == 0) {
                v0 *= alpha; v1 *= alpha; v2 *= alpha; v3 *= alpha;
            }
            p0[0] = v0; p0[1] = v1; p1[0] = v2; p1[1] = v3;
        }
    }
    if (mode == 1 && part) {
        red[tid] = lmax; __syncthreads();
        for (int s = 128; s > 0; s >>= 1) {
            if (tid < s) red[tid] = fmaxf(red[tid], red[tid + s]);
            __syncthreads();
        }
        if (tid == 0) part[blockIdx.y * gridDim.x + blockIdx.x] = red[0];
    }
}

// ======= int8 mma.sync GEMM NT (exact): C = alpha*(A8@B8^T) + bias[col] ======
// 128x128 tile, K-chunk 128 int8 (128-byte rows, same swizzle), 2-stage.
__global__ __launch_bounds__(256)
void ic_gemm(const signed char* __restrict__ A8, const signed char* __restrict__ B8,
             int K, float* __restrict__ C, const float* __restrict__ bias,
             const float* __restrict__ scal, int M) {
    extern __shared__ char dsm[];
    const int tid = threadIdx.x, l = tid & 31, w = tid >> 5;
    const int bm = blockIdx.y * 128, bn = blockIdx.x * 128;
    const int wm = (w & 1) * 64, wn = (w >> 1) * 32;
    const int kchunks = K >> 7;               // 128 int8 per chunk
    const uint32_t sbase = smem_u32(dsm);     // stage = 2 tiles * 16KB = 32KB

    int acc[4][4][4];
#pragma unroll
    for (int i = 0; i < 4; i++)
#pragma unroll
        for (int j = 0; j < 4; j++)
#pragma unroll
            for (int k = 0; k < 4; k++) acc[i][j][k] = 0;

    const int lr = tid >> 3, lg = tid & 7;
    {
        const signed char* ga = A8 + (size_t)(bm + lr) * K + lg * 16;
        const signed char* gb = B8 + (size_t)(bn + lr) * K + lg * 16;
#pragma unroll
        for (int i = 0; i < 4; i++) {
            cp16(sw_addr(sbase, lr + i * 32, lg), ga + (size_t)i * 32 * K);
            cp16(sw_addr(sbase + 16384u, lr + i * 32, lg), gb + (size_t)i * 32 * K);
        }
    }
    CP_COMMIT();
    CP_WAIT0();
    __syncthreads();

    for (int ch = 0; ch < kchunks; ch++) {
        const uint32_t st = sbase + (uint32_t)(ch & 1) * 32768u;
        if (ch + 1 < kchunks) {
            const uint32_t nst = sbase + (uint32_t)((ch + 1) & 1) * 32768u;
            const signed char* ga = A8 + (size_t)(bm + lr) * K + (ch + 1) * 128 + lg * 16;
            const signed char* gb = B8 + (size_t)(bn + lr) * K + (ch + 1) * 128 + lg * 16;
#pragma unroll
            for (int i = 0; i < 4; i++) {
                cp16(sw_addr(nst, lr + i * 32, lg), ga + (size_t)i * 32 * K);
                cp16(sw_addr(nst + 16384u, lr + i * 32, lg), gb + (size_t)i * 32 * K);
            }
            CP_COMMIT();
        }
        const uint32_t sA = st, sB = st + 16384u;
        const int rA = wm + (l & 15);
        const int rB = wn + (l & 7) + ((l & 16) ? 8 : 0);
#pragma unroll
        for (int ks = 0; ks < 4; ks++) {           // 4 x k32 per 128B chunk
            uint32_t a[4][4], b[2][4];
            const int gA = ks * 2 + (l >> 4);
            const int gB = ks * 2 + ((l >> 3) & 1);
#pragma unroll
            for (int mt = 0; mt < 4; mt++)
                LDSM4(a[mt][0], a[mt][1], a[mt][2], a[mt][3], sw_addr(sA, rA + mt * 16, gA));
#pragma unroll
            for (int bp = 0; bp < 2; bp++)
                LDSM4(b[bp][0], b[bp][1], b[bp][2], b[bp][3], sw_addr(sB, rB + bp * 16, gB));
#pragma unroll
            for (int mt = 0; mt < 4; mt++)
#pragma unroll
                for (int nt = 0; nt < 4; nt++)
                    MMA_S8(acc[mt][nt], a[mt], b[nt >> 1][(nt & 1) * 2], b[nt >> 1][(nt & 1) * 2 + 1]);
        }
        if (ch + 1 < kchunks) CP_WAIT0();
        __syncthreads();
    }

    const float alpha = scal[3] * __fdiv_rn(scal[1], 127.0f);
    const int rr = bm + wm + (l >> 2);
    const int cbs = bn + wn + (l & 3) * 2;
#pragma unroll
    for (int mt = 0; mt < 4; mt++) {
        int r0 = rr + mt * 16;
#pragma unroll
        for (int nt = 0; nt < 4; nt++) {
            int cc = cbs + nt * 8;
            float b0 = bias[cc], b1 = bias[cc + 1];
            float* p0 = C + (size_t)r0 * M + cc;
            float* p1 = p0 + (size_t)8 * M;
            p0[0] = (float)acc[mt][nt][0] * alpha + b0;
            p0[1] = (float)acc[mt][nt][1] * alpha + b1;
            p1[0] = (float)acc[mt][nt][2] * alpha + b0;
            p1[1] = (float)acc[mt][nt][3] * alpha + b1;
        }
    }
}

// ---------------- launch -----------------------------------------------------
extern "C" void kernel_launch(void* const* d_in, const int* in_sizes, int n_in,
                              void* d_out, int out_size) {
    const float* x  = (const float*)d_in[0];
    const float* mk = (const float*)d_in[1];
    const float* mv = (const float*)d_in[2];
    const float* Wk = (const float*)d_in[3];
    const float* bk = (const float*)d_in[4];
    // d_in[5], d_in[6] (Wv, bv) dead: _query_values never reaches output.
    const float* Wo = (const float*)d_in[7];
    const float* bo = (const float*)d_in[8];
    float* out = (float*)d_out;

    void *a0,*a1,*a2,*a3,*a4,*a6,*a7,*a8,*a9,*a10,*a11,*a12,*a13,*a14,*a15,*a16;
    cudaGetSymbolAddress(&a0, g_part);  cudaGetSymbolAddress(&a1, g_scal);
    cudaGetSymbolAddress(&a2, g_qxb);   cudaGetSymbolAddress(&a3, g_qwkT);
    cudaGetSymbolAddress(&a4, g_qwo8);
    cudaGetSymbolAddress(&a6, g_ghi);   cudaGetSymbolAddress(&a7, g_glo);
    cudaGetSymbolAddress(&a8, g_mhiT);  cudaGetSymbolAddress(&a9, g_mloT);
    cudaGetSymbolAddress(&a10, g_c);    cudaGetSymbolAddress(&a11, g_sim);
    cudaGetSymbolAddress(&a12, g_ahi);  cudaGetSymbolAddress(&a13, g_alo);
    cudaGetSymbolAddress(&a14, g_h);    cudaGetSymbolAddress(&a15, g_mkhi);
    cudaGetSymbolAddress(&a16, g_mklo);
    float* part = (float*)a0;  float* scal = (float*)a1;
    bf16* qxb = (bf16*)a2;     bf16* qwkT = (bf16*)a3;
    signed char* qwo8 = (signed char*)a4;
    bf16* ghi = (bf16*)a6;     bf16* glo = (bf16*)a7;
    bf16* mhiT = (bf16*)a8;    bf16* mloT = (bf16*)a9;
    float* cvec = (float*)a10; float* sim = (float*)a11;
    bf16* ahi = (bf16*)a12;    bf16* alo = (bf16*)a13;
    float* h = (float*)a14;
    bf16* mkhi = (bf16*)a15;   bf16* mklo = (bf16*)a16;
    signed char* qh8 = (signed char*)a2;   // reuse qxb storage after sim GEMM

    const size_t nx = (size_t)NROWS * EDIM;
    const size_t nw = (size_t)EDIM * EDIM;
    const size_t ng = (size_t)MSIZE * EDIM;
    cudaFuncSetAttribute(tc_gemm, cudaFuncAttributeMaxDynamicSharedMemorySize, 131072);
    cudaFuncSetAttribute(ic_gemm, cudaFuncAttributeMaxDynamicSharedMemorySize, 65536);

    // 0: fused prologue (x absmax + Wk/Wo abssum partials + mk split)
    prep_all<<<3072 + (unsigned)((ng + 255) / 256), 256>>>(x, mk, Wk, Wo, mkhi, mklo, part);
    // 1: xmax, wsk, wso
    finalize3<<<1, 256>>>(part, scal);
    // 2: quantize+transpose Wk -> bf16 [i,d]
    tq_wkT<<<dim3(32, 32), dim3(32, 8)>>>(Wk, qwkT, scal);
    // 3: G = mkhi@qwkT^T + mklo@qwkT^T, split epilogue -> ghi/glo
    tc_gemm<<<dim3(EDIM / 128, MSIZE / 128), 256, 3 * 32768>>>(
        mkhi, mklo, qwkT, nullptr, 2, 1, 0b0101, EDIM,
        nullptr, nullptr, scal, nullptr, 3, EDIM, ghi, glo);
    // 4: qx bf16
    quantize_act_bf16<<<(unsigned)(nx / 4 / 256), 256>>>(x, qxb, scal + 0, nx / 4);
    // 5: qWo int8
    quantize_w_i8<<<(unsigned)(nw / 4 / 256), 256>>>(Wo, qwo8, scal + 3, nw / 4);
    // 6: mv transpose+split
    transpose_split<<<dim3(EDIM / 32, MSIZE / 32), dim3(32, 8)>>>(mv, mhiT, mloT);
    // 7: bias fold vector
    cvec_k<<<MSIZE / 8, 256>>>(mk, bk, cvec);
    // 8: sim = alpha0 * (qx@Ghi^T + qx@Glo^T)  [fused]
    tc_gemm<<<dim3(MSIZE / 128, NROWS / 128), 256, 3 * 32768>>>(
        qxb, nullptr, ghi, glo, 1, 2, 0b0011, EDIM,
        sim, nullptr, scal, nullptr, 0, MSIZE, nullptr, nullptr);
    // 9: softmax -> attn hi/lo
    softmax_split<<<NROWS, 256>>>(sim, cvec, ahi, alo);
    // 10: h = x + (ahi+alo)@mhi
    tc_gemm<<<dim3(EDIM / 128, NROWS / 128), 256, 3 * 32768>>>(
        ahi, alo, mhiT, nullptr, 2, 1, 0b0101, MSIZE,
        h, x, scal, nullptr, 1, EDIM, nullptr, nullptr);
    // 11: h += ahi@mlo + fused absmax
    tc_gemm<<<dim3(EDIM / 128, NROWS / 128), 256, 2 * 32768>>>(
        ahi, nullptr, mloT, nullptr, 1, 1, 0b0001, MSIZE,
        h, h, scal, part, 1, EDIM, nullptr, nullptr);
    // 12: hmax
    finalize_max<<<1, 256>>>(part, (EDIM / 128) * (NROWS / 128), scal + 1);
    // 13: qh int8 (reuses qxb storage; sim GEMM already consumed qxb)
    quantize_act_i8<<<(unsigned)(nx / 4 / 256), 256>>>(h, qh8, scal + 1, nx / 4);
    // 14: out = alpha2 * (qh@qWo^T) + bo   [exact int8 tensor cores]
    ic_gemm<<<dim3(EDIM / 128, NROWS / 128), 256, 65536>>>(
        qh8, qwo8, EDIM, out, bo, scal, EDIM);
}

// round 15
// speedup vs baseline: 1.1302x; 1.1302x over previous
#include <cuda_runtime.h>
#include <cuda_bf16.h>
#include <cstddef>
#include <cstdint>

#define NROWS 32768
#define EDIM  1024
#define MSIZE 2048
typedef __nv_bfloat16 bf16;

// ---------------- scratch ----------------------------------------------------
__device__ float g_part[4096];
__device__ float g_scal[8];           // 0 xmax, 1 hmax, 2 wsk, 3 wso
__device__ bf16  g_qxb [(size_t)NROWS * EDIM];    // qx / qh as exact-int bf16
__device__ bf16  g_qwkT[(size_t)EDIM * EDIM];     // quantized Wk, transposed [i,d]
__device__ bf16  g_qwob[(size_t)EDIM * EDIM];     // quantized Wo [o,i]
__device__ bf16  g_mkhi[(size_t)MSIZE * EDIM];
__device__ bf16  g_mklo[(size_t)MSIZE * EDIM];
__device__ bf16  g_ghi [(size_t)MSIZE * EDIM];
__device__ bf16  g_glo [(size_t)MSIZE * EDIM];
__device__ bf16  g_mhiT[(size_t)EDIM * MSIZE];
__device__ bf16  g_mloT[(size_t)EDIM * MSIZE];
__device__ float g_c   [MSIZE];
__device__ float g_sim [(size_t)NROWS * MSIZE];
__device__ bf16  g_ahi [(size_t)NROWS * MSIZE];
__device__ bf16  g_alo [(size_t)NROWS * MSIZE];
__device__ float g_h   [(size_t)NROWS * EDIM];

// ---------------- helpers ----------------------------------------------------
__device__ __forceinline__ uint32_t smem_u32(const void* p) {
    uint32_t a;
    asm("{ .reg .u64 t; cvta.to.shared.u64 t, %1; cvt.u32.u64 %0, t; }" : "=r"(a) : "l"(p));
    return a;
}
// 128B-row swizzle: 16B unit g ^= (row & 7)
__device__ __forceinline__ uint32_t sw_addr(uint32_t base, int r, int g) {
    return base + r * 128 + ((g ^ (r & 7)) << 4);
}
__device__ __forceinline__ void cp16(uint32_t s, const void* g) {
    asm volatile("cp.async.cg.shared.global [%0], [%1], 16;" :: "r"(s), "l"(g));
}
#define CP_COMMIT() asm volatile("cp.async.commit_group;" ::: "memory")
#define CP_WAIT0()  asm volatile("cp.async.wait_group 0;" ::: "memory")
#define LDSM4(r0, r1, r2, r3, addr) \
    asm volatile("ldmatrix.sync.aligned.m8n8.x4.shared.b16 {%0,%1,%2,%3}, [%4];" \
                 : "=r"(r0), "=r"(r1), "=r"(r2), "=r"(r3) : "r"(addr))
#define MMA_BF16(c, a, b0r, b1r) \
    asm volatile("mma.sync.aligned.m16n8k16.row.col.f32.bf16.bf16.f32 " \
                 "{%0,%1,%2,%3}, {%4,%5,%6,%7}, {%8,%9}, {%0,%1,%2,%3};" \
                 : "+f"((c)[0]), "+f"((c)[1]), "+f"((c)[2]), "+f"((c)[3]) \
                 : "r"((a)[0]), "r"((a)[1]), "r"((a)[2]), "r"((a)[3]), "r"(b0r), "r"(b1r))

// ---------------- fused prologue ---------------------------------------------
// blocks [0,2048): x absmax -> part[0..2048)
// [2048,2560): Wk abssum -> part[2048+] ; [2560,3072): Wo abssum -> part[2560+]
// [3072, 3072+8192): mk split -> mkhi/mklo
__global__ void prep_all(const float* __restrict__ x, const float* __restrict__ mk,
                         const float* __restrict__ Wk, const float* __restrict__ Wo,
                         bf16* __restrict__ mkhi, bf16* __restrict__ mklo,
                         float* __restrict__ part) {
    const int b = blockIdx.x, tid = threadIdx.x;
    __shared__ float red[256];
    if (b < 2048) {
        const float4* x4 = (const float4*)x;
        const size_t n4 = (size_t)NROWS * EDIM / 4;
        float m = 0.f;
        for (size_t i = (size_t)b * 256 + tid; i < n4; i += (size_t)2048 * 256) {
            float4 v = x4[i];
            m = fmaxf(m, fmaxf(fmaxf(fabsf(v.x), fabsf(v.y)), fmaxf(fabsf(v.z), fabsf(v.w))));
        }
        red[tid] = m; __syncthreads();
        for (int s = 128; s > 0; s >>= 1) {
            if (tid < s) red[tid] = fmaxf(red[tid], red[tid + s]);
            __syncthreads();
        }
        if (tid == 0) part[b] = red[0];
    } else if (b < 3072) {
        const float4* w4 = (const float4*)(b < 2560 ? Wk : Wo);
        const int bb = (b < 2560) ? b - 2048 : b - 2560;
        const size_t n4 = (size_t)EDIM * EDIM / 4;
        float s = 0.f;
        for (size_t i = (size_t)bb * 256 + tid; i < n4; i += (size_t)512 * 256) {
            float4 v = w4[i];
            s += fabsf(v.x) + fabsf(v.y) + fabsf(v.z) + fabsf(v.w);
        }
        red[tid] = s; __syncthreads();
        for (int st = 128; st > 0; st >>= 1) {
            if (tid < st) red[tid] += red[tid + st];
            __syncthreads();
        }
        if (tid == 0) part[(b < 2560 ? 2048 : 2560) + bb] = red[0];
    } else {
        size_t i = (size_t)(b - 3072) * 256 + tid;
        if (i < (size_t)MSIZE * EDIM) {
            float v = mk[i];
            bf16 h = __float2bfloat16(v);
            mkhi[i] = h;
            mklo[i] = __float2bfloat16(v - __bfloat162float(h));
        }
    }
}

// xmax, wsk, wso in one block
__global__ void finalize3(const float* __restrict__ part, float* __restrict__ scal) {
    __shared__ float red[256];
    const int tid = threadIdx.x;
    const float n = (float)((size_t)EDIM * EDIM);
    float m = 0.f;
    for (int i = tid; i < 2048; i += 256) m = fmaxf(m, part[i]);
    red[tid] = m; __syncthreads();
    for (int s = 128; s > 0; s >>= 1) {
        if (tid < s) red[tid] = fmaxf(red[tid], red[tid + s]);
        __syncthreads();
    }
    if (tid == 0) scal[0] = red[0];
    __syncthreads();
    float s1 = 0.f;
    for (int i = tid; i < 512; i += 256) s1 += part[2048 + i];
    red[tid] = s1; __syncthreads();
    for (int st = 128; st > 0; st >>= 1) {
        if (tid < st) red[tid] += red[tid + st];
        __syncthreads();
    }
    if (tid == 0) scal[2] = __fdiv_rn(red[0], n);
    __syncthreads();
    float s2 = 0.f;
    for (int i = tid; i < 512; i += 256) s2 += part[2560 + i];
    red[tid] = s2; __syncthreads();
    for (int st = 128; st > 0; st >>= 1) {
        if (tid < st) red[tid] += red[tid + st];
        __syncthreads();
    }
    if (tid == 0) scal[3] = __fdiv_rn(red[0], n);
}

__global__ void finalize_max(const float* __restrict__ part, int npart, float* __restrict__ out) {
    __shared__ float red[256];
    float m = 0.f;
    for (int i = threadIdx.x; i < npart; i += 256) m = fmaxf(m, part[i]);
    red[threadIdx.x] = m; __syncthreads();
    for (int s = 128; s > 0; s >>= 1) {
        if (threadIdx.x < s) red[threadIdx.x] = fmaxf(red[threadIdx.x], red[threadIdx.x + s]);
        __syncthreads();
    }
    if (threadIdx.x == 0) out[0] = red[0];
}

// ---------------- quantize / split / transpose -------------------------------
__global__ void quantize_act_bf16(const float* __restrict__ x, bf16* __restrict__ q,
                                  const float* __restrict__ amax, size_t n4) {
    size_t i = (size_t)blockIdx.x * blockDim.x + threadIdx.x;
    if (i >= n4) return;
    float iscale = __fdiv_rn(amax[0], 127.0f);
    float4 v = ((const float4*)x)[i];
    float r0 = fminf(fmaxf(rintf(__fdiv_rn(v.x, iscale)), -128.f), 127.f);
    float r1 = fminf(fmaxf(rintf(__fdiv_rn(v.y, iscale)), -128.f), 127.f);
    float r2 = fminf(fmaxf(rintf(__fdiv_rn(v.z, iscale)), -128.f), 127.f);
    float r3 = fminf(fmaxf(rintf(__fdiv_rn(v.w, iscale)), -128.f), 127.f);
    bf16* o = q + i * 4;
    o[0] = __float2bfloat16(r0); o[1] = __float2bfloat16(r1);
    o[2] = __float2bfloat16(r2); o[3] = __float2bfloat16(r3);
}

__global__ void quantize_w_bf16(const float* __restrict__ W, bf16* __restrict__ q,
                                const float* __restrict__ wscale, size_t n) {
    size_t i = (size_t)blockIdx.x * blockDim.x + threadIdx.x;
    if (i >= n) return;
    float thr = 0.5f * wscale[0];
    float v = W[i];
    float o = (fabsf(v) > thr) ? (v > 0.f ? 1.f : -1.f) : 0.f;
    q[i] = __float2bfloat16(o);
}

// quantize Wk to bf16 ternary, transposed: q[i,d] = quant(W[d,i])
__global__ void tq_wkT(const float* __restrict__ W, bf16* __restrict__ q,
                       const float* __restrict__ scal) {
    __shared__ float t[32][33];
    int bd = blockIdx.y * 32, bi = blockIdx.x * 32;
    for (int j = threadIdx.y; j < 32; j += 8)
        t[j][threadIdx.x] = W[(size_t)(bd + j) * EDIM + bi + threadIdx.x];
    __syncthreads();
    float thr = 0.5f * scal[2];
    for (int j = threadIdx.y; j < 32; j += 8) {
        float v = t[threadIdx.x][j];
        float o = (fabsf(v) > thr) ? (v > 0.f ? 1.f : -1.f) : 0.f;
        q[(size_t)(bi + j) * EDIM + bd + threadIdx.x] = __float2bfloat16(o);
    }
}

// mv [MSIZE, EDIM] -> transposed split [EDIM, MSIZE]
__global__ void transpose_split(const float* __restrict__ mv, bf16* __restrict__ hi,
                                bf16* __restrict__ lo) {
    __shared__ float t[32][33];
    int bx = blockIdx.x * 32, by = blockIdx.y * 32;
    for (int i = threadIdx.y; i < 32; i += 8)
        t[i][threadIdx.x] = mv[(size_t)(by + i) * EDIM + bx + threadIdx.x];
    __syncthreads();
    for (int i = threadIdx.y; i < 32; i += 8) {
        float v = t[threadIdx.x][i];
        bf16 h = __float2bfloat16(v);
        size_t o = (size_t)(bx + i) * MSIZE + by + threadIdx.x;
        hi[o] = h;
        lo[o] = __float2bfloat16(v - __bfloat162float(h));
    }
}

__global__ void cvec_k(const float* __restrict__ mk, const float* __restrict__ bk,
                       float* __restrict__ c) {
    int m = blockIdx.x * 8 + (threadIdx.x >> 5);
    int lane = threadIdx.x & 31;
    const float4* row = (const float4*)(mk + (size_t)m * EDIM);
    const float4* b4 = (const float4*)bk;
    float s = 0.f;
    for (int i = lane; i < EDIM / 4; i += 32) {
        float4 a = row[i], b = b4[i];
        s += a.x * b.x + a.y * b.y + a.z * b.z + a.w * b.w;
    }
    for (int o = 16; o > 0; o >>= 1) s += __shfl_xor_sync(0xffffffffu, s, o);
    if (lane == 0) c[m] = s;
}

// -------- row softmax (+ c[m]/32), emit 2-level bf16 attn --------------------
__global__ void softmax_split(const float* __restrict__ S, const float* __restrict__ c,
                              bf16* __restrict__ ahi, bf16* __restrict__ alo) {
    const size_t row = blockIdx.x;
    const float* p = S + row * (size_t)MSIZE;
    const int tid = threadIdx.x;
    float v[8];
#pragma unroll
    for (int i = 0; i < 8; i++) v[i] = p[tid + i * 256] + c[tid + i * 256] * 0.03125f;
    float m = v[0];
#pragma unroll
    for (int i = 1; i < 8; i++) m = fmaxf(m, v[i]);
    __shared__ float red[256];
    red[tid] = m; __syncthreads();
    for (int s = 128; s > 0; s >>= 1) {
        if (tid < s) red[tid] = fmaxf(red[tid], red[tid + s]);
        __syncthreads();
    }
    const float rowmax = red[0];
    __syncthreads();
    float sum = 0.f;
#pragma unroll
    for (int i = 0; i < 8; i++) { v[i] = expf(v[i] - rowmax); sum += v[i]; }
    red[tid] = sum; __syncthreads();
    for (int s = 128; s > 0; s >>= 1) {
        if (tid < s) red[tid] += red[tid + s];
        __syncthreads();
    }
    const float inv = __fdiv_rn(1.0f, red[0]);
#pragma unroll
    for (int i = 0; i < 8; i++) {
        float a = v[i] * inv;
        bf16 h = __float2bfloat16(a);
        size_t o = row * (size_t)MSIZE + tid + i * 256;
        ahi[o] = h;
        alo[o] = __float2bfloat16(a - __bfloat162float(h));
    }
}

// ======= bf16 mma.sync GEMM NT, 128x128 tile, term-fused single K-sweep ======
// D = sum over terms t in tmask of At[bm..,K] @ Bt[bn..,K]^T  (fp32 accum)
// term bit t: ai = t>>1 in {A0,A1}, bi = t&1 in {B0,B1}
// mode 0: C = D*alpha0 ; mode 1: C = D + aux, absmax->part if part!=null ;
// mode 2: C = D*alpha2 + aux[col] ; mode 3: (Ohi,Olo) = split(D)
__global__ __launch_bounds__(256)
void tc_gemm(const bf16* A0, const bf16* A1, const bf16* B0, const bf16* B1,
             int nA, int nB, int tmask, int K,
             float* __restrict__ C, const float* __restrict__ aux,
             const float* __restrict__ scal, float* __restrict__ part,
             int mode, int M, bf16* __restrict__ Ohi, bf16* __restrict__ Olo) {
    extern __shared__ char dsm[];
    __shared__ float red[256];
    const int tid = threadIdx.x, l = tid & 31, w = tid >> 5;
    const int bm = blockIdx.y * 128, bn = blockIdx.x * 128;
    const int wm = (w & 1) * 64, wn = (w >> 1) * 32;
    const int kchunks = K >> 6;
    const int ntiles = nA + nB;
    const uint32_t stageBytes = (uint32_t)ntiles * 16384u;
    const uint32_t sbase = smem_u32(dsm);

    const bf16* tp[4]; int rbase[4];
    {
        int n = 0;
        tp[n] = A0; rbase[n] = bm; n++;
        if (nA > 1) { tp[n] = A1; rbase[n] = bm; n++; }
        tp[n] = B0; rbase[n] = bn; n++;
        if (nB > 1) { tp[n] = B1; rbase[n] = bn; n++; }
    }

    float acc[4][4][4];
#pragma unroll
    for (int i = 0; i < 4; i++)
#pragma unroll
        for (int j = 0; j < 4; j++)
#pragma unroll
            for (int k = 0; k < 4; k++) acc[i][j][k] = 0.f;

    const int lr = tid >> 3, lg = tid & 7;
    for (int t = 0; t < ntiles; t++) {
        const bf16* gp = tp[t] + (size_t)(rbase[t] + lr) * K + lg * 8;
        uint32_t s = sbase + t * 16384u;
#pragma unroll
        for (int i = 0; i < 4; i++)
            cp16(sw_addr(s, lr + i * 32, lg), gp + (size_t)i * 32 * K);
    }
    CP_COMMIT();
    CP_WAIT0();
    __syncthreads();

    for (int ch = 0; ch < kchunks; ch++) {
        const uint32_t st = sbase + (uint32_t)(ch & 1) * stageBytes;
        if (ch + 1 < kchunks) {
            const uint32_t nst = sbase + (uint32_t)((ch + 1) & 1) * stageBytes;
            for (int t = 0; t < ntiles; t++) {
                const bf16* gp = tp[t] + (size_t)(rbase[t] + lr) * K + (ch + 1) * 64 + lg * 8;
                uint32_t s = nst + t * 16384u;
#pragma unroll
                for (int i = 0; i < 4; i++)
                    cp16(sw_addr(s, lr + i * 32, lg), gp + (size_t)i * 32 * K);
            }
            CP_COMMIT();
        }
        const int rA = wm + (l & 15);
        const int rB = wn + (l & 7) + ((l & 16) ? 8 : 0);
        for (int t = 0; t < 4; t++) {
            if (!((tmask >> t) & 1)) continue;
            const uint32_t sA = st + (uint32_t)(t >> 1) * 16384u;
            const uint32_t sB = st + (uint32_t)(nA + (t & 1)) * 16384u;
#pragma unroll
            for (int ks = 0; ks < 4; ks++) {
                uint32_t a[4][4], b[2][4];
                const int gA = ks * 2 + (l >> 4);
                const int gB = ks * 2 + ((l >> 3) & 1);
#pragma unroll
                for (int mt = 0; mt < 4; mt++)
                    LDSM4(a[mt][0], a[mt][1], a[mt][2], a[mt][3], sw_addr(sA, rA + mt * 16, gA));
#pragma unroll
                for (int bp = 0; bp < 2; bp++)
                    LDSM4(b[bp][0], b[bp][1], b[bp][2], b[bp][3], sw_addr(sB, rB + bp * 16, gB));
#pragma unroll
                for (int mt = 0; mt < 4; mt++)
#pragma unroll
                    for (int nt = 0; nt < 4; nt++)
                        MMA_BF16(acc[mt][nt], a[mt], b[nt >> 1][(nt & 1) * 2], b[nt >> 1][(nt & 1) * 2 + 1]);
            }
        }
        if (ch + 1 < kchunks) CP_WAIT0();
        __syncthreads();
    }

    float alpha = 1.f;
    if (mode == 0) alpha = 0.03125f * scal[2] * __fdiv_rn(scal[0], 127.0f);
    else if (mode == 2) alpha = scal[3] * __fdiv_rn(scal[1], 127.0f);
    float lmax = 0.f;
    const int rr = bm + wm + (l >> 2);
    const int cbs = bn + wn + (l & 3) * 2;
#pragma unroll
    for (int mt = 0; mt < 4; mt++) {
        int r0 = rr + mt * 16;
#pragma unroll
        for (int nt = 0; nt < 4; nt++) {
            int cc = cbs + nt * 8;
            float v0 = acc[mt][nt][0], v1 = acc[mt][nt][1];
            float v2 = acc[mt][nt][2], v3 = acc[mt][nt][3];
            if (mode == 3) {
                bf16 h0 = __float2bfloat16(v0), h1 = __float2bfloat16(v1);
                bf16 h2 = __float2bfloat16(v2), h3 = __float2bfloat16(v3);
                size_t o0 = (size_t)r0 * M + cc, o1 = (size_t)(r0 + 8) * M + cc;
                Ohi[o0] = h0; Ohi[o0 + 1] = h1; Ohi[o1] = h2; Ohi[o1 + 1] = h3;
                Olo[o0] = __float2bfloat16(v0 - __bfloat162float(h0));
                Olo[o0 + 1] = __float2bfloat16(v1 - __bfloat162float(h1));
                Olo[o1] = __float2bfloat16(v2 - __bfloat162float(h2));
                Olo[o1 + 1] = __float2bfloat16(v3 - __bfloat162float(h3));
                continue;
            }
            float* p0 = C + (size_t)r0 * M + cc;
            float* p1 = p0 + (size_t)8 * M;
            if (mode == 1) {
                const float* x0 = aux + (size_t)r0 * M + cc;
                const float* x1 = x0 + (size_t)8 * M;
                v0 += x0[0]; v1 += x0[1]; v2 += x1[0]; v3 += x1[1];
                lmax = fmaxf(lmax, fmaxf(fmaxf(fabsf(v0), fabsf(v1)), fmaxf(fabsf(v2), fabsf(v3))));
            } else if (mode == 0) {
                v0 *= alpha; v1 *= alpha; v2 *= alpha; v3 *= alpha;
            } else if (mode == 2) {
                float b0 = aux[cc], b1 = aux[cc + 1];
                v0 = v0 * alpha + b0; v1 = v1 * alpha + b1;
                v2 = v2 * alpha + b0; v3 = v3 * alpha + b1;
            }
            p0[0] = v0; p0[1] = v1; p1[0] = v2; p1[1] = v3;
        }
    }
    if (mode == 1 && part) {
        red[tid] = lmax; __syncthreads();
        for (int s = 128; s > 0; s >>= 1) {
            if (tid < s) red[tid] = fmaxf(red[tid], red[tid + s]);
            __syncthreads();
        }
        if (tid == 0) part[blockIdx.y * gridDim.x + blockIdx.x] = red[0];
    }
}

// ---------------- launch -----------------------------------------------------
extern "C" void kernel_launch(void* const* d_in, const int* in_sizes, int n_in,
                              void* d_out, int out_size) {
    const float* x  = (const float*)d_in[0];
    const float* mk = (const float*)d_in[1];
    const float* mv = (const float*)d_in[2];
    const float* Wk = (const float*)d_in[3];
    const float* bk = (const float*)d_in[4];
    // d_in[5], d_in[6] (Wv, bv) dead: _query_values never reaches output.
    const float* Wo = (const float*)d_in[7];
    const float* bo = (const float*)d_in[8];
    float* out = (float*)d_out;

    void *a0,*a1,*a2,*a3,*a4,*a6,*a7,*a8,*a9,*a10,*a11,*a12,*a13,*a14,*a15,*a16;
    cudaGetSymbolAddress(&a0, g_part);  cudaGetSymbolAddress(&a1, g_scal);
    cudaGetSymbolAddress(&a2, g_qxb);   cudaGetSymbolAddress(&a3, g_qwkT);
    cudaGetSymbolAddress(&a4, g_qwob);
    cudaGetSymbolAddress(&a6, g_ghi);   cudaGetSymbolAddress(&a7, g_glo);
    cudaGetSymbolAddress(&a8, g_mhiT);  cudaGetSymbolAddress(&a9, g_mloT);
    cudaGetSymbolAddress(&a10, g_c);    cudaGetSymbolAddress(&a11, g_sim);
    cudaGetSymbolAddress(&a12, g_ahi);  cudaGetSymbolAddress(&a13, g_alo);
    cudaGetSymbolAddress(&a14, g_h);    cudaGetSymbolAddress(&a15, g_mkhi);
    cudaGetSymbolAddress(&a16, g_mklo);
    float* part = (float*)a0;  float* scal = (float*)a1;
    bf16* qxb = (bf16*)a2;     bf16* qwkT = (bf16*)a3;
    bf16* qwob = (bf16*)a4;
    bf16* ghi = (bf16*)a6;     bf16* glo = (bf16*)a7;
    bf16* mhiT = (bf16*)a8;    bf16* mloT = (bf16*)a9;
    float* cvec = (float*)a10; float* sim = (float*)a11;
    bf16* ahi = (bf16*)a12;    bf16* alo = (bf16*)a13;
    float* h = (float*)a14;
    bf16* mkhi = (bf16*)a15;   bf16* mklo = (bf16*)a16;

    const size_t nx = (size_t)NROWS * EDIM;
    const size_t nw = (size_t)EDIM * EDIM;
    const size_t ng = (size_t)MSIZE * EDIM;
    cudaFuncSetAttribute(tc_gemm, cudaFuncAttributeMaxDynamicSharedMemorySize, 131072);

    // 0: fused prologue (x absmax + Wk/Wo abssum partials + mk split)
    prep_all<<<3072 + (unsigned)((ng + 255) / 256), 256>>>(x, mk, Wk, Wo, mkhi, mklo, part);
    // 1: xmax, wsk, wso
    finalize3<<<1, 256>>>(part, scal);
    // 2: quantize+transpose Wk -> bf16 [i,d]
    tq_wkT<<<dim3(32, 32), dim3(32, 8)>>>(Wk, qwkT, scal);
    // 3: G = mkhi@qwkT^T + mklo@qwkT^T, split epilogue -> ghi/glo
    tc_gemm<<<dim3(EDIM / 128, MSIZE / 128), 256, 3 * 32768>>>(
        mkhi, mklo, qwkT, nullptr, 2, 1, 0b0101, EDIM,
        nullptr, nullptr, scal, nullptr, 3, EDIM, ghi, glo);
    // 4: qx bf16
    quantize_act_bf16<<<(unsigned)(nx / 4 / 256), 256>>>(x, qxb, scal + 0, nx / 4);
    // 5: qWo bf16
    quantize_w_bf16<<<(unsigned)(nw / 256), 256>>>(Wo, qwob, scal + 3, nw);
    // 6: mv transpose+split
    transpose_split<<<dim3(EDIM / 32, MSIZE / 32), dim3(32, 8)>>>(mv, mhiT, mloT);
    // 7: bias fold vector
    cvec_k<<<MSIZE / 8, 256>>>(mk, bk, cvec);
    // 8: sim = alpha0 * (qx@Ghi^T + qx@Glo^T)  [fused]
    tc_gemm<<<dim3(MSIZE / 128, NROWS / 128), 256, 3 * 32768>>>(
        qxb, nullptr, ghi, glo, 1, 2, 0b0011, EDIM,
        sim, nullptr, scal, nullptr, 0, MSIZE, nullptr, nullptr);
    // 9: softmax -> attn hi/lo
    softmax_split<<<NROWS, 256>>>(sim, cvec, ahi, alo);
    // 10: h = x + ahi@mhi + ahi@mlo + alo@mhi  [fused 3-term] + block absmax
    tc_gemm<<<dim3(EDIM / 128, NROWS / 128), 256, 4 * 32768>>>(
        ahi, alo, mhiT, mloT, 2, 2, 0b0111, MSIZE,
        h, x, scal, part, 1, EDIM, nullptr, nullptr);
    // 11: hmax
    finalize_max<<<1, 256>>>(part, (EDIM / 128) * (NROWS / 128), scal + 1);
    // 12: qh bf16
    quantize_act_bf16<<<(unsigned)(nx / 4 / 256), 256>>>(h, qxb, scal + 1, nx / 4);
    // 13: out = alpha2 * qh @ qWo^T + bo  [exact]
    tc_gemm<<<dim3(EDIM / 128, NROWS / 128), 256, 2 * 32768>>>(
        qxb, nullptr, qwob, nullptr, 1, 1, 0b0001, EDIM,
        out, bo, scal, nullptr, 2, EDIM, nullptr, nullptr);
}

// round 16
// speedup vs baseline: 1.1351x; 1.0043x over previous
#include <cuda_runtime.h>
#include <cuda_bf16.h>
#include <cstddef>
#include <cstdint>

#define NROWS 32768
#define EDIM  1024
#define MSIZE 2048
typedef __nv_bfloat16 bf16;

// ---------------- scratch ----------------------------------------------------
__device__ float g_part[4096];
__device__ float g_scal[8];           // 0 xmax, 1 hmax, 2 wsk, 3 wso
__device__ bf16  g_qxb [(size_t)NROWS * EDIM];
__device__ bf16  g_qwkT[(size_t)EDIM * EDIM];
__device__ bf16  g_qwob[(size_t)EDIM * EDIM];
__device__ bf16  g_mkhi[(size_t)MSIZE * EDIM];
__device__ bf16  g_mklo[(size_t)MSIZE * EDIM];
__device__ bf16  g_ghi [(size_t)MSIZE * EDIM];
__device__ bf16  g_glo [(size_t)MSIZE * EDIM];
__device__ bf16  g_mhiT[(size_t)EDIM * MSIZE];
__device__ bf16  g_mloT[(size_t)EDIM * MSIZE];
__device__ float g_c   [MSIZE];
__device__ float g_sim [(size_t)NROWS * MSIZE];
__device__ bf16  g_ahi [(size_t)NROWS * MSIZE];
__device__ bf16  g_alo [(size_t)NROWS * MSIZE];
__device__ float g_h   [(size_t)NROWS * EDIM];

// ---------------- helpers ----------------------------------------------------
__device__ __forceinline__ uint32_t smem_u32(const void* p) {
    uint32_t a;
    asm("{ .reg .u64 t; cvta.to.shared.u64 t, %1; cvt.u32.u64 %0, t; }" : "=r"(a) : "l"(p));
    return a;
}
__device__ __forceinline__ uint32_t sw_addr(uint32_t base, int r, int g) {
    return base + r * 128 + ((g ^ (r & 7)) << 4);
}
__device__ __forceinline__ void cp16(uint32_t s, const void* g) {
    asm volatile("cp.async.cg.shared.global [%0], [%1], 16;" :: "r"(s), "l"(g));
}
#define CP_COMMIT() asm volatile("cp.async.commit_group;" ::: "memory")
#define CP_WAIT0()  asm volatile("cp.async.wait_group 0;" ::: "memory")
#define LDSM4(r0, r1, r2, r3, addr) \
    asm volatile("ldmatrix.sync.aligned.m8n8.x4.shared.b16 {%0,%1,%2,%3}, [%4];" \
                 : "=r"(r0), "=r"(r1), "=r"(r2), "=r"(r3) : "r"(addr))
#define MMA_BF16(c, a, b0r, b1r) \
    asm volatile("mma.sync.aligned.m16n8k16.row.col.f32.bf16.bf16.f32 " \
                 "{%0,%1,%2,%3}, {%4,%5,%6,%7}, {%8,%9}, {%0,%1,%2,%3};" \
                 : "+f"((c)[0]), "+f"((c)[1]), "+f"((c)[2]), "+f"((c)[3]) \
                 : "r"((a)[0]), "r"((a)[1]), "r"((a)[2]), "r"((a)[3]), "r"(b0r), "r"(b1r))

// ---------------- fused prologue ---------------------------------------------
// [0,2048): x absmax ; [2048,2560): Wk abssum ; [2560,3072): Wo abssum
// [3072,11264): mk split ; [11264,13312): mv transpose+split ; [13312,13568): cvec
__global__ void prep_all(const float* __restrict__ x, const float* __restrict__ mk,
                         const float* __restrict__ mv,
                         const float* __restrict__ Wk, const float* __restrict__ Wo,
                         const float* __restrict__ bk,
                         bf16* __restrict__ mkhi, bf16* __restrict__ mklo,
                         bf16* __restrict__ mhiT, bf16* __restrict__ mloT,
                         float* __restrict__ cvec, float* __restrict__ part) {
    const int b = blockIdx.x, tid = threadIdx.x;
    __shared__ float red[256];
    __shared__ float tsp[32][33];
    if (b < 2048) {
        const float4* x4 = (const float4*)x;
        const size_t n4 = (size_t)NROWS * EDIM / 4;
        float m = 0.f;
        for (size_t i = (size_t)b * 256 + tid; i < n4; i += (size_t)2048 * 256) {
            float4 v = x4[i];
            m = fmaxf(m, fmaxf(fmaxf(fabsf(v.x), fabsf(v.y)), fmaxf(fabsf(v.z), fabsf(v.w))));
        }
        red[tid] = m; __syncthreads();
        for (int s = 128; s > 0; s >>= 1) {
            if (tid < s) red[tid] = fmaxf(red[tid], red[tid + s]);
            __syncthreads();
        }
        if (tid == 0) part[b] = red[0];
    } else if (b < 3072) {
        const float4* w4 = (const float4*)(b < 2560 ? Wk : Wo);
        const int bb = (b < 2560) ? b - 2048 : b - 2560;
        const size_t n4 = (size_t)EDIM * EDIM / 4;
        float s = 0.f;
        for (size_t i = (size_t)bb * 256 + tid; i < n4; i += (size_t)512 * 256) {
            float4 v = w4[i];
            s += fabsf(v.x) + fabsf(v.y) + fabsf(v.z) + fabsf(v.w);
        }
        red[tid] = s; __syncthreads();
        for (int st = 128; st > 0; st >>= 1) {
            if (tid < st) red[tid] += red[tid + st];
            __syncthreads();
        }
        if (tid == 0) part[(b < 2560 ? 2048 : 2560) + bb] = red[0];
    } else if (b < 11264) {
        size_t i = (size_t)(b - 3072) * 256 + tid;
        float v = mk[i];
        bf16 h = __float2bfloat16(v);
        mkhi[i] = h;
        mklo[i] = __float2bfloat16(v - __bfloat162float(h));
    } else if (b < 13312) {
        const int bb = b - 11264;
        const int bx = (bb & 31) * 32;     // e block
        const int by = (bb >> 5) * 32;     // m block
        const int tx = tid & 31, ty = tid >> 5;
        for (int i = ty; i < 32; i += 8)
            tsp[i][tx] = mv[(size_t)(by + i) * EDIM + bx + tx];
        __syncthreads();
        for (int i = ty; i < 32; i += 8) {
            float v = tsp[tx][i];
            bf16 h = __float2bfloat16(v);
            size_t o = (size_t)(bx + i) * MSIZE + by + tx;
            mhiT[o] = h;
            mloT[o] = __float2bfloat16(v - __bfloat162float(h));
        }
    } else {
        const int bb = b - 13312;
        int m = bb * 8 + (tid >> 5);
        int lane = tid & 31;
        const float4* row = (const float4*)(mk + (size_t)m * EDIM);
        const float4* b4 = (const float4*)bk;
        float s = 0.f;
        for (int i = lane; i < EDIM / 4; i += 32) {
            float4 a = row[i], bv = b4[i];
            s += a.x * bv.x + a.y * bv.y + a.z * bv.z + a.w * bv.w;
        }
        for (int o = 16; o > 0; o >>= 1) s += __shfl_xor_sync(0xffffffffu, s, o);
        if (lane == 0) cvec[m] = s;
    }
}

// xmax, wsk, wso in one block
__global__ void finalize3(const float* __restrict__ part, float* __restrict__ scal) {
    __shared__ float red[256];
    const int tid = threadIdx.x;
    const float n = (float)((size_t)EDIM * EDIM);
    float m = 0.f;
    for (int i = tid; i < 2048; i += 256) m = fmaxf(m, part[i]);
    red[tid] = m; __syncthreads();
    for (int s = 128; s > 0; s >>= 1) {
        if (tid < s) red[tid] = fmaxf(red[tid], red[tid + s]);
        __syncthreads();
    }
    if (tid == 0) scal[0] = red[0];
    __syncthreads();
    float s1 = 0.f;
    for (int i = tid; i < 512; i += 256) s1 += part[2048 + i];
    red[tid] = s1; __syncthreads();
    for (int st = 128; st > 0; st >>= 1) {
        if (tid < st) red[tid] += red[tid + st];
        __syncthreads();
    }
    if (tid == 0) scal[2] = __fdiv_rn(red[0], n);
    __syncthreads();
    float s2 = 0.f;
    for (int i = tid; i < 512; i += 256) s2 += part[2560 + i];
    red[tid] = s2; __syncthreads();
    for (int st = 128; st > 0; st >>= 1) {
        if (tid < st) red[tid] += red[tid + st];
        __syncthreads();
    }
    if (tid == 0) scal[3] = __fdiv_rn(red[0], n);
}

__global__ void finalize_max(const float* __restrict__ part, int npart, float* __restrict__ out) {
    __shared__ float red[256];
    float m = 0.f;
    for (int i = threadIdx.x; i < npart; i += 256) m = fmaxf(m, part[i]);
    red[threadIdx.x] = m; __syncthreads();
    for (int s = 128; s > 0; s >>= 1) {
        if (threadIdx.x < s) red[threadIdx.x] = fmaxf(red[threadIdx.x], red[threadIdx.x + s]);
        __syncthreads();
    }
    if (threadIdx.x == 0) out[0] = red[0];
}

// ---------------- weight quant (both) ----------------------------------------
// [0,1024): tq_wkT 32x32 tiles ; [1024,5120): qWo elementwise
__global__ void wq_all(const float* __restrict__ Wk, const float* __restrict__ Wo,
                       bf16* __restrict__ qwkT, bf16* __restrict__ qwob,
                       const float* __restrict__ scal) {
    const int b = blockIdx.x, tid = threadIdx.x;
    __shared__ float t[32][33];
    if (b < 1024) {
        const int bi = (b & 31) * 32, bd = (b >> 5) * 32;
        const int tx = tid & 31, ty = tid >> 5;
        for (int j = ty; j < 32; j += 8)
            t[j][tx] = Wk[(size_t)(bd + j) * EDIM + bi + tx];
        __syncthreads();
        float thr = 0.5f * scal[2];
        for (int j = ty; j < 32; j += 8) {
            float v = t[tx][j];
            float o = (fabsf(v) > thr) ? (v > 0.f ? 1.f : -1.f) : 0.f;
            qwkT[(size_t)(bi + j) * EDIM + bd + tx] = __float2bfloat16(o);
        }
    } else {
        size_t i = (size_t)(b - 1024) * 256 + tid;
        float thr = 0.5f * scal[3];
        float v = Wo[i];
        float o = (fabsf(v) > thr) ? (v > 0.f ? 1.f : -1.f) : 0.f;
        qwob[i] = __float2bfloat16(o);
    }
}

// ---------------- activation quantize ----------------------------------------
__global__ void quantize_act_bf16(const float* __restrict__ x, bf16* __restrict__ q,
                                  const float* __restrict__ amax, size_t n4) {
    size_t i = (size_t)blockIdx.x * blockDim.x + threadIdx.x;
    if (i >= n4) return;
    float iscale = __fdiv_rn(amax[0], 127.0f);
    float4 v = ((const float4*)x)[i];
    float r0 = fminf(fmaxf(rintf(__fdiv_rn(v.x, iscale)), -128.f), 127.f);
    float r1 = fminf(fmaxf(rintf(__fdiv_rn(v.y, iscale)), -128.f), 127.f);
    float r2 = fminf(fmaxf(rintf(__fdiv_rn(v.z, iscale)), -128.f), 127.f);
    float r3 = fminf(fmaxf(rintf(__fdiv_rn(v.w, iscale)), -128.f), 127.f);
    bf16* o = q + i * 4;
    o[0] = __float2bfloat16(r0); o[1] = __float2bfloat16(r1);
    o[2] = __float2bfloat16(r2); o[3] = __float2bfloat16(r3);
}

// -------- row softmax (+ c[m]/32), emit 2-level bf16 attn --------------------
__global__ void softmax_split(const float* __restrict__ S, const float* __restrict__ c,
                              bf16* __restrict__ ahi, bf16* __restrict__ alo) {
    const size_t row = blockIdx.x;
    const float* p = S + row * (size_t)MSIZE;
    const int tid = threadIdx.x;
    float v[8];
#pragma unroll
    for (int i = 0; i < 8; i++) v[i] = p[tid + i * 256] + c[tid + i * 256] * 0.03125f;
    float m = v[0];
#pragma unroll
    for (int i = 1; i < 8; i++) m = fmaxf(m, v[i]);
    __shared__ float red[256];
    red[tid] = m; __syncthreads();
    for (int s = 128; s > 0; s >>= 1) {
        if (tid < s) red[tid] = fmaxf(red[tid], red[tid + s]);
        __syncthreads();
    }
    const float rowmax = red[0];
    __syncthreads();
    float sum = 0.f;
#pragma unroll
    for (int i = 0; i < 8; i++) { v[i] = expf(v[i] - rowmax); sum += v[i]; }
    red[tid] = sum; __syncthreads();
    for (int s = 128; s > 0; s >>= 1) {
        if (tid < s) red[tid] += red[tid + s];
        __syncthreads();
    }
    const float inv = __fdiv_rn(1.0f, red[0]);
#pragma unroll
    for (int i = 0; i < 8; i++) {
        float a = v[i] * inv;
        bf16 h = __float2bfloat16(a);
        size_t o = row * (size_t)MSIZE + tid + i * 256;
        ahi[o] = h;
        alo[o] = __float2bfloat16(a - __bfloat162float(h));
    }
}

// ======= bf16 mma.sync GEMM NT, 128x128 tile, term-fused, A-frag hoisted =====
// D = sum over terms (ai,bi), bit (ai<<1)|bi of tmask, of A_ai @ B_bi^T.
// Term order (ai-major, bi-minor) preserves the previous accumulation order.
// mode 0: C=D*alpha0 ; 1: C=D+aux (+absmax->part) ; 2: C=D*alpha2+aux[col] ;
// mode 3: (Ohi,Olo)=split(D)
__global__ __launch_bounds__(256)
void tc_gemm(const bf16* A0, const bf16* A1, const bf16* B0, const bf16* B1,
             int nA, int nB, int tmask, int K,
             float* __restrict__ C, const float* __restrict__ aux,
             const float* __restrict__ scal, float* __restrict__ part,
             int mode, int M, bf16* __restrict__ Ohi, bf16* __restrict__ Olo) {
    extern __shared__ char dsm[];
    __shared__ float red[256];
    const int tid = threadIdx.x, l = tid & 31, w = tid >> 5;
    const int bm = blockIdx.y * 128, bn = blockIdx.x * 128;
    const int wm = (w & 1) * 64, wn = (w >> 1) * 32;
    const int kchunks = K >> 6;
    const int ntiles = nA + nB;
    const uint32_t stageBytes = (uint32_t)ntiles * 16384u;
    const uint32_t sbase = smem_u32(dsm);

    const bf16* tp[4]; int rbase[4];
    {
        int n = 0;
        tp[n] = A0; rbase[n] = bm; n++;
        if (nA > 1) { tp[n] = A1; rbase[n] = bm; n++; }
        tp[n] = B0; rbase[n] = bn; n++;
        if (nB > 1) { tp[n] = B1; rbase[n] = bn; n++; }
    }

    float acc[4][4][4];
#pragma unroll
    for (int i = 0; i < 4; i++)
#pragma unroll
        for (int j = 0; j < 4; j++)
#pragma unroll
            for (int k = 0; k < 4; k++) acc[i][j][k] = 0.f;

    const int lr = tid >> 3, lg = tid & 7;
    for (int t = 0; t < ntiles; t++) {
        const bf16* gp = tp[t] + (size_t)(rbase[t] + lr) * K + lg * 8;
        uint32_t s = sbase + t * 16384u;
#pragma unroll
        for (int i = 0; i < 4; i++)
            cp16(sw_addr(s, lr + i * 32, lg), gp + (size_t)i * 32 * K);
    }
    CP_COMMIT();
    CP_WAIT0();
    __syncthreads();

    for (int ch = 0; ch < kchunks; ch++) {
        const uint32_t st = sbase + (uint32_t)(ch & 1) * stageBytes;
        if (ch + 1 < kchunks) {
            const uint32_t nst = sbase + (uint32_t)((ch + 1) & 1) * stageBytes;
            for (int t = 0; t < ntiles; t++) {
                const bf16* gp = tp[t] + (size_t)(rbase[t] + lr) * K + (ch + 1) * 64 + lg * 8;
                uint32_t s = nst + t * 16384u;
#pragma unroll
                for (int i = 0; i < 4; i++)
                    cp16(sw_addr(s, lr + i * 32, lg), gp + (size_t)i * 32 * K);
            }
            CP_COMMIT();
        }
        const int rA = wm + (l & 15);
        const int rB = wn + (l & 7) + ((l & 16) ? 8 : 0);
#pragma unroll
        for (int ks = 0; ks < 4; ks++) {
            const int gA = ks * 2 + (l >> 4);
            const int gB = ks * 2 + ((l >> 3) & 1);
#pragma unroll
            for (int ai = 0; ai < 2; ai++) {
                const int pair = (tmask >> (ai * 2)) & 3;
                if (!pair) continue;
                const uint32_t sA = st + (uint32_t)ai * 16384u;
                uint32_t a[4][4];
#pragma unroll
                for (int mt = 0; mt < 4; mt++)
                    LDSM4(a[mt][0], a[mt][1], a[mt][2], a[mt][3], sw_addr(sA, rA + mt * 16, gA));
#pragma unroll
                for (int bi = 0; bi < 2; bi++) {
                    if (!((pair >> bi) & 1)) continue;
                    const uint32_t sB = st + (uint32_t)(nA + bi) * 16384u;
                    uint32_t bfr[2][4];
#pragma unroll
                    for (int bp = 0; bp < 2; bp++)
                        LDSM4(bfr[bp][0], bfr[bp][1], bfr[bp][2], bfr[bp][3],
                              sw_addr(sB, rB + bp * 16, gB));
#pragma unroll
                    for (int mt = 0; mt < 4; mt++)
#pragma unroll
                        for (int nt = 0; nt < 4; nt++)
                            MMA_BF16(acc[mt][nt], a[mt],
                                     bfr[nt >> 1][(nt & 1) * 2], bfr[nt >> 1][(nt & 1) * 2 + 1]);
                }
            }
        }
        if (ch + 1 < kchunks) CP_WAIT0();
        __syncthreads();
    }

    float alpha = 1.f;
    if (mode == 0) alpha = 0.03125f * scal[2] * __fdiv_rn(scal[0], 127.0f);
    else if (mode == 2) alpha = scal[3] * __fdiv_rn(scal[1], 127.0f);
    float lmax = 0.f;
    const int rr = bm + wm + (l >> 2);
    const int cbs = bn + wn + (l & 3) * 2;
#pragma unroll
    for (int mt = 0; mt < 4; mt++) {
        int r0 = rr + mt * 16;
#pragma unroll
        for (int nt = 0; nt < 4; nt++) {
            int cc = cbs + nt * 8;
            float v0 = acc[mt][nt][0], v1 = acc[mt][nt][1];
            float v2 = acc[mt][nt][2], v3 = acc[mt][nt][3];
            if (mode == 3) {
                bf16 h0 = __float2bfloat16(v0), h1 = __float2bfloat16(v1);
                bf16 h2 = __float2bfloat16(v2), h3 = __float2bfloat16(v3);
                size_t o0 = (size_t)r0 * M + cc, o1 = (size_t)(r0 + 8) * M + cc;
                Ohi[o0] = h0; Ohi[o0 + 1] = h1; Ohi[o1] = h2; Ohi[o1 + 1] = h3;
                Olo[o0] = __float2bfloat16(v0 - __bfloat162float(h0));
                Olo[o0 + 1] = __float2bfloat16(v1 - __bfloat162float(h1));
                Olo[o1] = __float2bfloat16(v2 - __bfloat162float(h2));
                Olo[o1 + 1] = __float2bfloat16(v3 - __bfloat162float(h3));
                continue;
            }
            float* p0 = C + (size_t)r0 * M + cc;
            float* p1 = p0 + (size_t)8 * M;
            if (mode == 1) {
                const float* x0 = aux + (size_t)r0 * M + cc;
                const float* x1 = x0 + (size_t)8 * M;
                v0 += x0[0]; v1 += x0[1]; v2 += x1[0]; v3 += x1[1];
                lmax = fmaxf(lmax, fmaxf(fmaxf(fabsf(v0), fabsf(v1)), fmaxf(fabsf(v2), fabsf(v3))));
            } else if (mode == 0) {
                v0 *= alpha; v1 *= alpha; v2 *= alpha; v3 *= alpha;
            } else if (mode == 2) {
                float b0 = aux[cc], b1 = aux[cc + 1];
                v0 = v0 * alpha + b0; v1 = v1 * alpha + b1;
                v2 = v2 * alpha + b0; v3 = v3 * alpha + b1;
            }
            p0[0] = v0; p0[1] = v1; p1[0] = v2; p1[1] = v3;
        }
    }
    if (mode == 1 && part) {
        red[tid] = lmax; __syncthreads();
        for (int s = 128; s > 0; s >>= 1) {
            if (tid < s) red[tid] = fmaxf(red[tid], red[tid + s]);
            __syncthreads();
        }
        if (tid == 0) part[blockIdx.y * gridDim.x + blockIdx.x] = red[0];
    }
}

// ---------------- launch -----------------------------------------------------
extern "C" void kernel_launch(void* const* d_in, const int* in_sizes, int n_in,
                              void* d_out, int out_size) {
    const float* x  = (const float*)d_in[0];
    const float* mk = (const float*)d_in[1];
    const float* mv = (const float*)d_in[2];
    const float* Wk = (const float*)d_in[3];
    const float* bk = (const float*)d_in[4];
    // d_in[5], d_in[6] (Wv, bv) dead: _query_values never reaches output.
    const float* Wo = (const float*)d_in[7];
    const float* bo = (const float*)d_in[8];
    float* out = (float*)d_out;

    void *a0,*a1,*a2,*a3,*a4,*a6,*a7,*a8,*a9,*a10,*a11,*a12,*a13,*a14,*a15,*a16;
    cudaGetSymbolAddress(&a0, g_part);  cudaGetSymbolAddress(&a1, g_scal);
    cudaGetSymbolAddress(&a2, g_qxb);   cudaGetSymbolAddress(&a3, g_qwkT);
    cudaGetSymbolAddress(&a4, g_qwob);
    cudaGetSymbolAddress(&a6, g_ghi);   cudaGetSymbolAddress(&a7, g_glo);
    cudaGetSymbolAddress(&a8, g_mhiT);  cudaGetSymbolAddress(&a9, g_mloT);
    cudaGetSymbolAddress(&a10, g_c);    cudaGetSymbolAddress(&a11, g_sim);
    cudaGetSymbolAddress(&a12, g_ahi);  cudaGetSymbolAddress(&a13, g_alo);
    cudaGetSymbolAddress(&a14, g_h);    cudaGetSymbolAddress(&a15, g_mkhi);
    cudaGetSymbolAddress(&a16, g_mklo);
    float* part = (float*)a0;  float* scal = (float*)a1;
    bf16* qxb = (bf16*)a2;     bf16* qwkT = (bf16*)a3;
    bf16* qwob = (bf16*)a4;
    bf16* ghi = (bf16*)a6;     bf16* glo = (bf16*)a7;
    bf16* mhiT = (bf16*)a8;    bf16* mloT = (bf16*)a9;
    float* cvec = (float*)a10; float* sim = (float*)a11;
    bf16* ahi = (bf16*)a12;    bf16* alo = (bf16*)a13;
    float* h = (float*)a14;
    bf16* mkhi = (bf16*)a15;   bf16* mklo = (bf16*)a16;

    const size_t nx = (size_t)NROWS * EDIM;
    cudaFuncSetAttribute(tc_gemm, cudaFuncAttributeMaxDynamicSharedMemorySize, 131072);

    // 0: fused prologue (x absmax + W abssums + mk split + mv transpose-split + cvec)
    prep_all<<<13568, 256>>>(x, mk, mv, Wk, Wo, bk, mkhi, mklo, mhiT, mloT, cvec, part);
    // 1: xmax, wsk, wso
    finalize3<<<1, 256>>>(part, scal);
    // 2: weight quant (Wk transpose-ternary + Wo ternary)
    wq_all<<<5120, 256>>>(Wk, Wo, qwkT, qwob, scal);
    // 3: G = mkhi@qwkT^T + mklo@qwkT^T, split epilogue -> ghi/glo
    tc_gemm<<<dim3(EDIM / 128, MSIZE / 128), 256, 3 * 32768>>>(
        mkhi, mklo, qwkT, nullptr, 2, 1, 0b0101, EDIM,
        nullptr, nullptr, scal, nullptr, 3, EDIM, ghi, glo);
    // 4: qx bf16
    quantize_act_bf16<<<(unsigned)(nx / 4 / 256), 256>>>(x, qxb, scal + 0, nx / 4);
    // 5: sim = alpha0 * (qx@Ghi^T + qx@Glo^T)
    tc_gemm<<<dim3(MSIZE / 128, NROWS / 128), 256, 3 * 32768>>>(
        qxb, nullptr, ghi, glo, 1, 2, 0b0011, EDIM,
        sim, nullptr, scal, nullptr, 0, MSIZE, nullptr, nullptr);
    // 6: softmax -> attn hi/lo
    softmax_split<<<NROWS, 256>>>(sim, cvec, ahi, alo);
    // 7: h = x + ahi@mhi + ahi@mlo + alo@mhi + block absmax
    tc_gemm<<<dim3(EDIM / 128, NROWS / 128), 256, 4 * 32768>>>(
        ahi, alo, mhiT, mloT, 2, 2, 0b0111, MSIZE,
        h, x, scal, part, 1, EDIM, nullptr, nullptr);
    // 8: hmax
    finalize_max<<<1, 256>>>(part, (EDIM / 128) * (NROWS / 128), scal + 1);
    // 9: qh bf16
    quantize_act_bf16<<<(unsigned)(nx / 4 / 256), 256>>>(h, qxb, scal + 1, nx / 4);
    // 10: out = alpha2 * qh @ qWo^T + bo  [exact]
    tc_gemm<<<dim3(EDIM / 128, NROWS / 128), 256, 2 * 32768>>>(
        qxb, nullptr, qwob, nullptr, 1, 1, 0b0001, EDIM,
        out, bo, scal, nullptr, 2, EDIM, nullptr, nullptr);
}